// round 6
// baseline (speedup 1.0000x reference)
#include <cuda_runtime.h>

// BasicRNN B=128, S=8000, H=64 — two-phase:
//  phase1: pure recurrence. 128 threads/block, 2 threads per row (each does a
//          32-wide half-dot as 16 packed f32x2 FMAs), combined with one
//          shfl_xor(1). Fully branch-free hot loop: both pair-threads write
//          identical values to the same smem/gmem addresses (benign dup).
//  phase2: parallel readout, 4 timesteps/iter via float4 loads, 1280 blocks.

#define BATCH 128
#define SEQ   8000
#define HID   64
#define CHUNK 1600
#define NCHUNK (SEQ / CHUNK)
#define GROUPS (SEQ / 4)        // 2000 groups of 4 timesteps
#define NCHK2 10                // phase2 chunks per batch
#define GCHK  (GROUPS / NCHK2)  // 200 groups per phase2 block
#define GWARP (GCHK / 8)        // 25 groups per warp

typedef unsigned long long ull;

// z scratch: [B][GROUPS][HID][4] = 262 MB
__device__ float g_z[(size_t)BATCH * GROUPS * HID * 4];
__device__ float g_pnum[BATCH * NCHK2];
__device__ float g_pden[BATCH * NCHK2];

__device__ __forceinline__ ull ffma2(ull a, ull b, ull c) {
    ull d;
    asm("fma.rn.f32x2 %0, %1, %2, %3;" : "=l"(d) : "l"(a), "l"(b), "l"(c));
    return d;
}
__device__ __forceinline__ ull fadd2(ull a, ull b) {
    ull d;
    asm("add.rn.f32x2 %0, %1, %2;" : "=l"(d) : "l"(a), "l"(b));
    return d;
}
__device__ __forceinline__ float lo32(ull a) { return __int_as_float((unsigned)a); }
__device__ __forceinline__ float hi32(ull a) { return __int_as_float((unsigned)(a >> 32)); }
__device__ __forceinline__ ull pack2(float lo, float hi) {
    return (ull)__float_as_uint(lo) | ((ull)__float_as_uint(hi) << 32);
}

__device__ __forceinline__ float tanh_hw(float z) {        // MUFU.TANH, 16 cyc
    float r;
    asm("tanh.approx.f32 %0, %1;" : "=f"(r) : "f"(z));
    return r;
}
__device__ __forceinline__ float tanh_prec(float z) {      // ~1e-6 abs err
    float e;
    asm("ex2.approx.f32 %0, %1;" : "=f"(e) : "f"(z * 2.8853900817779268f));
    float rcp;
    asm("rcp.approx.f32 %0, %1;" : "=f"(rcp) : "f"(e + 1.0f));
    return fmaf(-2.0f, rcp, 1.0f);
}
__device__ __forceinline__ float sigmoid_fast(float z) {
    float e;
    asm("ex2.approx.f32 %0, %1;" : "=f"(e) : "f"(z * -1.4426950408889634f));
    float rcp;
    asm("rcp.approx.f32 %0, %1;" : "=f"(rcp) : "f"(e + 1.0f));
    return rcp;
}

// ---------------- phase 1: recurrence (128 thr, 2 per row, branch-free) ----------------
__global__ void __launch_bounds__(128, 1)
rnn_phase1(const float* __restrict__ x,      // [B, S]
           const float* __restrict__ W_ih,   // [H, 1]
           const float* __restrict__ b_ih,   // [H]
           const float* __restrict__ W_hh,   // [H, H]
           const float* __restrict__ b_hh)   // [H]
{
    __shared__ __align__(16) float hb[2][HID];
    __shared__ float xs[CHUNK];

    const int b    = blockIdx.x;
    const int tid  = threadIdx.x;
    const int r    = tid >> 1;    // row 0..63
    const int half = tid & 1;     // which 32-wide half of h this lane covers

    // my 32 weights (half a row) as 16 packed f32x2
    ull w2[16];
    {
        const double* wp = (const double*)(W_hh + r * HID + half * 32);
        #pragma unroll
        for (int i = 0; i < 16; i++) w2[i] = __double_as_longlong(wp[i]);
    }
    const float wih_r  = W_ih[r];
    const float bias_r = b_ih[r] + b_hh[r];

    if (tid < HID) hb[0][tid] = 0.0f;   // h_0

    const float* xb = x + (long)b * SEQ;
    // both pair-threads point at the SAME slot; dup store is benign+coalesced
    float4* zp = (float4*)(g_z + (size_t)b * GROUPS * HID * 4) + r;

    __syncthreads();

    for (int c = 0; c < NCHUNK; ++c) {
        for (int i = tid; i < CHUNK; i += 128)
            xs[i] = xb[c * CHUNK + i];
        __syncthreads();

        #pragma unroll 1
        for (int s = 0; s < CHUNK; s += 4) {
            float zq[4];
            #pragma unroll
            for (int u = 0; u < 4; ++u) {
                const float* hsrc = hb[u & 1];
                float*       hdst = hb[(u & 1) ^ 1];
                const float  xp   = fmaf(xs[s + u], wih_r, bias_r);

                const double2* h2 = (const double2*)(hsrc + half * 32);
                // 4 packed accumulators; xp folded into a0 (SEL, no branch)
                ull a0 = half ? 0ull : pack2(xp, 0.0f);
                ull a1 = 0ull, a2 = 0ull, a3 = 0ull;
                #pragma unroll
                for (int i = 0; i < 4; i++) {
                    double2 va = h2[2 * i];
                    double2 vb = h2[2 * i + 1];
                    a0 = ffma2(w2[4 * i + 0], __double_as_longlong(va.x), a0);
                    a1 = ffma2(w2[4 * i + 1], __double_as_longlong(va.y), a1);
                    a2 = ffma2(w2[4 * i + 2], __double_as_longlong(vb.x), a2);
                    a3 = ffma2(w2[4 * i + 3], __double_as_longlong(vb.y), a3);
                }
                ull tS = fadd2(fadd2(a0, a1), fadd2(a2, a3));
                float sum = lo32(tS) + hi32(tS);
                float z   = sum + __shfl_xor_sync(0xffffffffu, sum, 1);

                zq[u] = z;
                hdst[r] = tanh_hw(z);   // both halves: same addr, same value
                __syncthreads();
            }
            *zp = make_float4(zq[0], zq[1], zq[2], zq[3]);  // dup-addr, coalesced
            zp += HID;
        }
    }
}

// ---------------- phase 2: parallel readout (1280 blocks) ----------------
__global__ void __launch_bounds__(256, 1)
rnn_phase2(const float* __restrict__ fc_w,   // [2, H]
           const float* __restrict__ fc_b)   // [2]
{
    __shared__ float snum[8], sden[8];

    const int bk   = blockIdx.x;
    const int b    = bk / NCHK2;             // batch
    const int ck   = bk % NCHK2;             // seq chunk
    const int w    = threadIdx.x >> 5;
    const int lane = threadIdx.x & 31;

    const float f0a = fc_w[lane];       const float f0b = fc_w[32 + lane];
    const float f1a = fc_w[64 + lane];  const float f1b = fc_w[96 + lane];
    const float fb0 = fc_b[0];          const float fb1 = fc_b[1];

    const float4* zb = (const float4*)(g_z +
        ((size_t)b * GROUPS + (size_t)ck * GCHK + (size_t)w * GWARP) * HID * 4);

    float num = 0.0f, den = 0.0f;
    #pragma unroll 1
    for (int i = 0; i < GWARP; ++i) {        // 25 groups = 100 timesteps
        const float4* zg = zb + (size_t)i * HID;
        float4 zA = zg[lane];                // rows 0..31, 4 steps
        float4 zB = zg[32 + lane];           // rows 32..63, 4 steps
        float p0[4], p1[4];
        {
            float a, bb;
            a = tanh_prec(zA.x); bb = tanh_prec(zB.x);
            p0[0] = fmaf(f0a, a, f0b * bb); p1[0] = fmaf(f1a, a, f1b * bb);
            a = tanh_prec(zA.y); bb = tanh_prec(zB.y);
            p0[1] = fmaf(f0a, a, f0b * bb); p1[1] = fmaf(f1a, a, f1b * bb);
            a = tanh_prec(zA.z); bb = tanh_prec(zB.z);
            p0[2] = fmaf(f0a, a, f0b * bb); p1[2] = fmaf(f1a, a, f1b * bb);
            a = tanh_prec(zA.w); bb = tanh_prec(zB.w);
            p0[3] = fmaf(f0a, a, f0b * bb); p1[3] = fmaf(f1a, a, f1b * bb);
        }
        #pragma unroll
        for (int o = 16; o > 0; o >>= 1) {
            #pragma unroll
            for (int j = 0; j < 4; j++) {
                p0[j] += __shfl_xor_sync(0xffffffffu, p0[j], o);
                p1[j] += __shfl_xor_sync(0xffffffffu, p1[j], o);
            }
        }
        #pragma unroll
        for (int j = 0; j < 4; j++) {
            float sel = sigmoid_fast(p0[j] + fb0);
            float sc  = sigmoid_fast(p1[j] + fb1);
            den += sel;
            num += sc * sel;
        }
    }
    if (lane == 0) { snum[w] = num; sden[w] = den; }
    __syncthreads();
    if (threadIdx.x == 0) {
        float N = 0.0f, D = 0.0f;
        #pragma unroll
        for (int i = 0; i < 8; i++) { N += snum[i]; D += sden[i]; }
        g_pnum[b * NCHK2 + ck] = N;
        g_pden[b * NCHK2 + ck] = D;
    }
}

// ---------------- phase 3: deterministic final reduce ----------------
__global__ void rnn_finish(float* __restrict__ out) {
    const int b = threadIdx.x;
    float N = 0.0f, D = 0.0f;
    #pragma unroll
    for (int i = 0; i < NCHK2; i++) {
        N += g_pnum[b * NCHK2 + i];
        D += g_pden[b * NCHK2 + i];
    }
    out[b] = __fdividef(N, D);
}

extern "C" void kernel_launch(void* const* d_in, const int* in_sizes, int n_in,
                              void* d_out, int out_size) {
    const float* x    = (const float*)d_in[0];
    const float* W_ih = (const float*)d_in[1];
    const float* b_ih = (const float*)d_in[2];
    const float* W_hh = (const float*)d_in[3];
    const float* b_hh = (const float*)d_in[4];
    const float* fc_w = (const float*)d_in[5];
    const float* fc_b = (const float*)d_in[6];
    float* out = (float*)d_out;
    (void)in_sizes; (void)n_in; (void)out_size;

    rnn_phase1<<<BATCH, 128>>>(x, W_ih, b_ih, W_hh, b_hh);
    rnn_phase2<<<BATCH * NCHK2, 256>>>(fc_w, fc_b);
    rnn_finish<<<1, BATCH>>>(out);
}

// round 7
// speedup vs baseline: 1.3048x; 1.3048x over previous
#include <cuda_runtime.h>

// BasicRNN B=128, S=8000, H=64 — two-phase (R5 architecture, tuned tail):
//  phase1: pure recurrence. 64 threads/block (one row per thread, 2 warps).
//          Broadcast LDS of h, 32 packed f32x2 FMAs into 4 accumulators,
//          MUFU.TANH, xp precomputed per 4-step group, z batched as STG.128.
//  phase2: parallel readout, 3200 blocks, float4 z loads, unroll 2.

#define BATCH 128
#define SEQ   8000
#define HID   64
#define CHUNK 1600
#define NCHUNK (SEQ / CHUNK)
#define GROUPS (SEQ / 4)        // 2000 groups of 4 timesteps
#define NCHK2 25                // phase2 chunks per batch
#define GCHK  (GROUPS / NCHK2)  // 80 groups per phase2 block
#define GWARP (GCHK / 8)        // 10 groups per warp

typedef unsigned long long ull;

// z scratch: [B][GROUPS][HID][4] = 262 MB
__device__ float g_z[(size_t)BATCH * GROUPS * HID * 4];
__device__ float g_pnum[BATCH * NCHK2];
__device__ float g_pden[BATCH * NCHK2];

__device__ __forceinline__ ull ffma2(ull a, ull b, ull c) {
    ull d;
    asm("fma.rn.f32x2 %0, %1, %2, %3;" : "=l"(d) : "l"(a), "l"(b), "l"(c));
    return d;
}
__device__ __forceinline__ ull fadd2(ull a, ull b) {
    ull d;
    asm("add.rn.f32x2 %0, %1, %2;" : "=l"(d) : "l"(a), "l"(b));
    return d;
}
__device__ __forceinline__ float lo32(ull a) { return __int_as_float((unsigned)a); }
__device__ __forceinline__ float hi32(ull a) { return __int_as_float((unsigned)(a >> 32)); }
__device__ __forceinline__ ull pack2(float lo, float hi) {
    return (ull)__float_as_uint(lo) | ((ull)__float_as_uint(hi) << 32);
}

__device__ __forceinline__ float tanh_hw(float z) {        // MUFU.TANH
    float r;
    asm("tanh.approx.f32 %0, %1;" : "=f"(r) : "f"(z));
    return r;
}
__device__ __forceinline__ float tanh_prec(float z) {      // ~1e-6 abs err
    float e;
    asm("ex2.approx.f32 %0, %1;" : "=f"(e) : "f"(z * 2.8853900817779268f));
    float rcp;
    asm("rcp.approx.f32 %0, %1;" : "=f"(rcp) : "f"(e + 1.0f));
    return fmaf(-2.0f, rcp, 1.0f);
}
__device__ __forceinline__ float sigmoid_fast(float z) {
    float e;
    asm("ex2.approx.f32 %0, %1;" : "=f"(e) : "f"(z * -1.4426950408889634f));
    float rcp;
    asm("rcp.approx.f32 %0, %1;" : "=f"(rcp) : "f"(e + 1.0f));
    return rcp;
}

// ---------------- phase 1: recurrence (64 threads, 1 row/thread) ----------------
__global__ void __launch_bounds__(64, 1)
rnn_phase1(const float* __restrict__ x,      // [B, S]
           const float* __restrict__ W_ih,   // [H, 1]
           const float* __restrict__ b_ih,   // [H]
           const float* __restrict__ W_hh,   // [H, H]
           const float* __restrict__ b_hh)   // [H]
{
    __shared__ __align__(16) float hb[2][HID];
    __shared__ float xs[CHUNK];

    const int b = blockIdx.x;
    const int r = threadIdx.x;   // row 0..63

    ull w2[32];                  // full W_hh row, packed f32x2
    {
        const double* wp = (const double*)(W_hh + r * HID);
        #pragma unroll
        for (int i = 0; i < 32; i++) w2[i] = __double_as_longlong(wp[i]);
    }
    const float wih_r  = W_ih[r];
    const float bias_r = b_ih[r] + b_hh[r];

    hb[0][r] = 0.0f;   // h_0

    const float* xb = x + (long)b * SEQ;
    float4* zp = (float4*)(g_z + (size_t)b * GROUPS * HID * 4) + r;

    __syncthreads();

    for (int c = 0; c < NCHUNK; ++c) {
        for (int i = r; i < CHUNK; i += 64)
            xs[i] = xb[c * CHUNK + i];
        __syncthreads();

        #pragma unroll 1
        for (int s = 0; s < CHUNK; s += 4) {
            // precompute all 4 x-projections up front (off the serial path)
            float xp[4];
            #pragma unroll
            for (int u = 0; u < 4; ++u)
                xp[u] = fmaf(xs[s + u], wih_r, bias_r);

            float zq[4];
            #pragma unroll
            for (int u = 0; u < 4; ++u) {
                const float* hsrc = hb[u & 1];
                float*       hdst = hb[(u & 1) ^ 1];

                const double2* h2 = (const double2*)hsrc;   // broadcast reads
                ull a0 = pack2(xp[u], 0.0f);
                ull a1 = 0ull, a2 = 0ull, a3 = 0ull;
                #pragma unroll
                for (int i = 0; i < 8; i++) {
                    double2 va = h2[2 * i];
                    double2 vb = h2[2 * i + 1];
                    a0 = ffma2(w2[4 * i + 0], __double_as_longlong(va.x), a0);
                    a1 = ffma2(w2[4 * i + 1], __double_as_longlong(va.y), a1);
                    a2 = ffma2(w2[4 * i + 2], __double_as_longlong(vb.x), a2);
                    a3 = ffma2(w2[4 * i + 3], __double_as_longlong(vb.y), a3);
                }
                ull tS = fadd2(fadd2(a0, a1), fadd2(a2, a3));
                float z = lo32(tS) + hi32(tS);

                zq[u]   = z;
                hdst[r] = tanh_hw(z);
                __syncthreads();
            }
            *zp = make_float4(zq[0], zq[1], zq[2], zq[3]);  // fire-and-forget
            zp += HID;
        }
    }
}

// ---------------- phase 2: parallel readout (3200 blocks) ----------------
__global__ void __launch_bounds__(256, 1)
rnn_phase2(const float* __restrict__ fc_w,   // [2, H]
           const float* __restrict__ fc_b)   // [2]
{
    __shared__ float snum[8], sden[8];

    const int bk   = blockIdx.x;
    const int b    = bk / NCHK2;             // batch
    const int ck   = bk % NCHK2;             // seq chunk
    const int w    = threadIdx.x >> 5;
    const int lane = threadIdx.x & 31;

    const float f0a = fc_w[lane];       const float f0b = fc_w[32 + lane];
    const float f1a = fc_w[64 + lane];  const float f1b = fc_w[96 + lane];
    const float fb0 = fc_b[0];          const float fb1 = fc_b[1];

    const float4* zb = (const float4*)(g_z +
        ((size_t)b * GROUPS + (size_t)ck * GCHK + (size_t)w * GWARP) * HID * 4);

    float num = 0.0f, den = 0.0f;
    #pragma unroll 2
    for (int i = 0; i < GWARP; ++i) {        // 10 groups = 40 timesteps
        const float4* zg = zb + (size_t)i * HID;
        float4 zA = zg[lane];                // rows 0..31, 4 steps
        float4 zB = zg[32 + lane];           // rows 32..63, 4 steps
        float p0[4], p1[4];
        {
            float a, bb;
            a = tanh_prec(zA.x); bb = tanh_prec(zB.x);
            p0[0] = fmaf(f0a, a, f0b * bb); p1[0] = fmaf(f1a, a, f1b * bb);
            a = tanh_prec(zA.y); bb = tanh_prec(zB.y);
            p0[1] = fmaf(f0a, a, f0b * bb); p1[1] = fmaf(f1a, a, f1b * bb);
            a = tanh_prec(zA.z); bb = tanh_prec(zB.z);
            p0[2] = fmaf(f0a, a, f0b * bb); p1[2] = fmaf(f1a, a, f1b * bb);
            a = tanh_prec(zA.w); bb = tanh_prec(zB.w);
            p0[3] = fmaf(f0a, a, f0b * bb); p1[3] = fmaf(f1a, a, f1b * bb);
        }
        #pragma unroll
        for (int o = 16; o > 0; o >>= 1) {
            #pragma unroll
            for (int j = 0; j < 4; j++) {
                p0[j] += __shfl_xor_sync(0xffffffffu, p0[j], o);
                p1[j] += __shfl_xor_sync(0xffffffffu, p1[j], o);
            }
        }
        #pragma unroll
        for (int j = 0; j < 4; j++) {
            float sel = sigmoid_fast(p0[j] + fb0);
            float sc  = sigmoid_fast(p1[j] + fb1);
            den += sel;
            num += sc * sel;
        }
    }
    if (lane == 0) { snum[w] = num; sden[w] = den; }
    __syncthreads();
    if (threadIdx.x == 0) {
        float N = 0.0f, D = 0.0f;
        #pragma unroll
        for (int i = 0; i < 8; i++) { N += snum[i]; D += sden[i]; }
        g_pnum[b * NCHK2 + ck] = N;
        g_pden[b * NCHK2 + ck] = D;
    }
}

// ---------------- phase 3: deterministic final reduce ----------------
__global__ void rnn_finish(float* __restrict__ out) {
    const int b = threadIdx.x;
    float N = 0.0f, D = 0.0f;
    #pragma unroll
    for (int i = 0; i < NCHK2; i++) {
        N += g_pnum[b * NCHK2 + i];
        D += g_pden[b * NCHK2 + i];
    }
    out[b] = __fdividef(N, D);
}

extern "C" void kernel_launch(void* const* d_in, const int* in_sizes, int n_in,
                              void* d_out, int out_size) {
    const float* x    = (const float*)d_in[0];
    const float* W_ih = (const float*)d_in[1];
    const float* b_ih = (const float*)d_in[2];
    const float* W_hh = (const float*)d_in[3];
    const float* b_hh = (const float*)d_in[4];
    const float* fc_w = (const float*)d_in[5];
    const float* fc_b = (const float*)d_in[6];
    float* out = (float*)d_out;
    (void)in_sizes; (void)n_in; (void)out_size;

    rnn_phase1<<<BATCH, 64>>>(x, W_ih, b_ih, W_hh, b_hh);
    rnn_phase2<<<BATCH * NCHK2, 256>>>(fc_w, fc_b);
    rnn_finish<<<1, BATCH>>>(out);
}

// round 8
// speedup vs baseline: 1.3752x; 1.0540x over previous
#include <cuda_runtime.h>

// BasicRNN B=128, S=8000, H=64 — fused overlap:
//  rec blocks (bid 0..127): R7 phase1 recurrence, 64 active threads, publishes
//       per-chunk progress (fence + volatile flag).
//  readout blocks (bid 128..3327): poll progress, then process a 320-step
//       slice of z (tanh -> fc -> sigmoid -> partial sums), OVERLAPPED with
//       the recurrence. Low-MUFU activations to limit interference.
//  finish kernel: deterministic final reduce.

#define BATCH 128
#define SEQ   8000
#define HID   64
#define CHUNK 1600
#define NCHUNK (SEQ / CHUNK)
#define GROUPS (SEQ / 4)        // 2000 groups of 4 timesteps
#define NCHK2 25                // readout chunks per batch
#define GCHK  (GROUPS / NCHK2)  // 80 groups per readout block
#define GWARP (GCHK / 8)        // 10 groups per warp

typedef unsigned long long ull;

// z scratch: [B][GROUPS][HID][4] = 262 MB
__device__ float g_z[(size_t)BATCH * GROUPS * HID * 4];
__device__ float g_pnum[BATCH * NCHK2];
__device__ float g_pden[BATCH * NCHK2];
__device__ volatile unsigned g_prog[BATCH];   // steps completed per batch

__device__ __forceinline__ ull ffma2(ull a, ull b, ull c) {
    ull d;
    asm("fma.rn.f32x2 %0, %1, %2, %3;" : "=l"(d) : "l"(a), "l"(b), "l"(c));
    return d;
}
__device__ __forceinline__ ull fadd2(ull a, ull b) {
    ull d;
    asm("add.rn.f32x2 %0, %1, %2;" : "=l"(d) : "l"(a), "l"(b));
    return d;
}
__device__ __forceinline__ float lo32(ull a) { return __int_as_float((unsigned)a); }
__device__ __forceinline__ float hi32(ull a) { return __int_as_float((unsigned)(a >> 32)); }
__device__ __forceinline__ ull pack2(float lo, float hi) {
    return (ull)__float_as_uint(lo) | ((ull)__float_as_uint(hi) << 32);
}

__device__ __forceinline__ float tanh_hw(float z) {        // MUFU.TANH
    float r;
    asm("tanh.approx.f32 %0, %1;" : "=f"(r) : "f"(z));
    return r;
}
__device__ __forceinline__ float sigmoid_tanh(float x) {   // 1 MUFU
    return fmaf(0.5f, tanh_hw(0.5f * x), 0.5f);
}

// ---------------- init: reset progress flags ----------------
__global__ void rnn_init() {
    g_prog[threadIdx.x] = 0u;
}

// ---------------- fused recurrence + overlapped readout ----------------
__global__ void __launch_bounds__(256, 1)
rnn_fused(const float* __restrict__ x,      // [B, S]
          const float* __restrict__ W_ih,   // [H, 1]
          const float* __restrict__ b_ih,   // [H]
          const float* __restrict__ W_hh,   // [H, H]
          const float* __restrict__ b_hh,   // [H]
          const float* __restrict__ fc_w,   // [2, H]
          const float* __restrict__ fc_b)   // [2]
{
    const int bid = blockIdx.x;
    const int tid = threadIdx.x;

    if (bid < BATCH) {
        // ================= recurrence block =================
        if (tid >= 64) return;           // 64 active threads, 2 warps
        __shared__ __align__(16) float hb[2][HID];
        __shared__ float xs[CHUNK];

        const int b = bid;
        const int r = tid;               // row 0..63

        ull w2[32];                      // full W_hh row, packed f32x2
        {
            const double* wp = (const double*)(W_hh + r * HID);
            #pragma unroll
            for (int i = 0; i < 32; i++) w2[i] = __double_as_longlong(wp[i]);
        }
        const float wih_r  = W_ih[r];
        const float bias_r = b_ih[r] + b_hh[r];

        hb[0][r] = 0.0f;   // h_0

        const float* xb = x + (long)b * SEQ;
        float4* zp = (float4*)(g_z + (size_t)b * GROUPS * HID * 4) + r;

        __syncthreads();

        for (int c = 0; c < NCHUNK; ++c) {
            for (int i = r; i < CHUNK; i += 64)
                xs[i] = xb[c * CHUNK + i];
            __syncthreads();

            #pragma unroll 1
            for (int s = 0; s < CHUNK; s += 4) {
                float xp[4];
                #pragma unroll
                for (int u = 0; u < 4; ++u)
                    xp[u] = fmaf(xs[s + u], wih_r, bias_r);

                float zq[4];
                #pragma unroll
                for (int u = 0; u < 4; ++u) {
                    const float* hsrc = hb[u & 1];
                    float*       hdst = hb[(u & 1) ^ 1];

                    const double2* h2 = (const double2*)hsrc;   // broadcast
                    ull a0 = pack2(xp[u], 0.0f);
                    ull a1 = 0ull, a2 = 0ull, a3 = 0ull;
                    #pragma unroll
                    for (int i = 0; i < 8; i++) {
                        double2 va = h2[2 * i];
                        double2 vb = h2[2 * i + 1];
                        a0 = ffma2(w2[4 * i + 0], __double_as_longlong(va.x), a0);
                        a1 = ffma2(w2[4 * i + 1], __double_as_longlong(va.y), a1);
                        a2 = ffma2(w2[4 * i + 2], __double_as_longlong(vb.x), a2);
                        a3 = ffma2(w2[4 * i + 3], __double_as_longlong(vb.y), a3);
                    }
                    ull tS = fadd2(fadd2(a0, a1), fadd2(a2, a3));
                    float z = lo32(tS) + hi32(tS);

                    zq[u]   = z;
                    hdst[r] = tanh_hw(z);
                    __syncthreads();
                }
                *zp = make_float4(zq[0], zq[1], zq[2], zq[3]);  // fire-and-forget
                zp += HID;
            }

            // publish progress (once per 1600 steps): order all threads' STGs
            __syncthreads();
            if (r == 0) {
                __threadfence();                       // gpu-scope, cumulative
                g_prog[b] = (unsigned)((c + 1) * CHUNK);
            }
        }
    } else {
        // ================= readout block =================
        __shared__ float snum[8], sden[8];

        const int bk   = bid - BATCH;            // ck-major: early blocks need early data
        const int ck   = bk / BATCH;             // seq chunk 0..24
        const int b    = bk % BATCH;             // batch
        const int w    = tid >> 5;
        const int lane = tid & 31;

        // wait until this chunk's z is published
        const unsigned need = (unsigned)((ck + 1) * GCHK * 4);
        if (tid == 0) {
            while (g_prog[b] < need) __nanosleep(1024);
        }
        __syncthreads();
        __threadfence();                         // acquire side

        const float f0a = fc_w[lane];       const float f0b = fc_w[32 + lane];
        const float f1a = fc_w[64 + lane];  const float f1b = fc_w[96 + lane];
        const float fb0 = fc_b[0];          const float fb1 = fc_b[1];

        const float4* zb = (const float4*)(g_z +
            ((size_t)b * GROUPS + (size_t)ck * GCHK + (size_t)w * GWARP) * HID * 4);

        float num = 0.0f, den = 0.0f;
        #pragma unroll 2
        for (int i = 0; i < GWARP; ++i) {        // 10 groups = 40 timesteps
            const float4* zg = zb + (size_t)i * HID;
            float4 zA = zg[lane];                // rows 0..31, 4 steps
            float4 zB = zg[32 + lane];           // rows 32..63, 4 steps
            float p0[4], p1[4];
            {
                float a, bb;
                a = tanh_hw(zA.x); bb = tanh_hw(zB.x);
                p0[0] = fmaf(f0a, a, f0b * bb); p1[0] = fmaf(f1a, a, f1b * bb);
                a = tanh_hw(zA.y); bb = tanh_hw(zB.y);
                p0[1] = fmaf(f0a, a, f0b * bb); p1[1] = fmaf(f1a, a, f1b * bb);
                a = tanh_hw(zA.z); bb = tanh_hw(zB.z);
                p0[2] = fmaf(f0a, a, f0b * bb); p1[2] = fmaf(f1a, a, f1b * bb);
                a = tanh_hw(zA.w); bb = tanh_hw(zB.w);
                p0[3] = fmaf(f0a, a, f0b * bb); p1[3] = fmaf(f1a, a, f1b * bb);
            }
            #pragma unroll
            for (int o = 16; o > 0; o >>= 1) {
                #pragma unroll
                for (int j = 0; j < 4; j++) {
                    p0[j] += __shfl_xor_sync(0xffffffffu, p0[j], o);
                    p1[j] += __shfl_xor_sync(0xffffffffu, p1[j], o);
                }
            }
            #pragma unroll
            for (int j = 0; j < 4; j++) {
                float sel = sigmoid_tanh(p0[j] + fb0);
                float sc  = sigmoid_tanh(p1[j] + fb1);
                den += sel;
                num += sc * sel;
            }
        }
        if (lane == 0) { snum[w] = num; sden[w] = den; }
        __syncthreads();
        if (tid == 0) {
            float N = 0.0f, D = 0.0f;
            #pragma unroll
            for (int i = 0; i < 8; i++) { N += snum[i]; D += sden[i]; }
            g_pnum[b * NCHK2 + ck] = N;
            g_pden[b * NCHK2 + ck] = D;
        }
    }
}

// ---------------- deterministic final reduce ----------------
__global__ void rnn_finish(float* __restrict__ out) {
    const int b = threadIdx.x;
    float N = 0.0f, D = 0.0f;
    #pragma unroll
    for (int i = 0; i < NCHK2; i++) {
        N += g_pnum[b * NCHK2 + i];
        D += g_pden[b * NCHK2 + i];
    }
    out[b] = __fdividef(N, D);
}

extern "C" void kernel_launch(void* const* d_in, const int* in_sizes, int n_in,
                              void* d_out, int out_size) {
    const float* x    = (const float*)d_in[0];
    const float* W_ih = (const float*)d_in[1];
    const float* b_ih = (const float*)d_in[2];
    const float* W_hh = (const float*)d_in[3];
    const float* b_hh = (const float*)d_in[4];
    const float* fc_w = (const float*)d_in[5];
    const float* fc_b = (const float*)d_in[6];
    float* out = (float*)d_out;
    (void)in_sizes; (void)n_in; (void)out_size;

    rnn_init<<<1, BATCH>>>();
    rnn_fused<<<BATCH + BATCH * NCHK2, 256>>>(x, W_ih, b_ih, W_hh, b_hh, fc_w, fc_b);
    rnn_finish<<<1, BATCH>>>(out);
}